// round 2
// baseline (speedup 1.0000x reference)
#include <cuda_runtime.h>
#include <cuda_bf16.h>

// Problem dims (fixed by the dataset; N/E taken from in_sizes at runtime).
#define NMAX 100000
#define EMAX 1600000
#define DIM  128
#define HID  64
#define NG   64

// ---------------- device scratch (no allocations allowed) ----------------
__device__ float g_deg[NMAX];
__device__ float g_dinv[NMAX];
__device__ int   g_cnt[NMAX];
__device__ int   g_off[NMAX];
__device__ int   g_cur[NMAX];
__device__ int   g_bsum[1024];
__device__ int   g_csc_row[EMAX];
__device__ float g_csc_w[EMAX];
__device__ __align__(16) float g_bufA[(size_t)NMAX * HID];
__device__ __align__(16) float g_bufB[(size_t)NMAX * HID];
__device__ float g_psum[NG * HID];
__device__ float g_pcnt[NG];

// ---------------- init: deg=1 (self loop), counts=0, pool accum=0 ----------------
__global__ void k_init(int n) {
    int i = blockIdx.x * blockDim.x + threadIdx.x;
    if (i < n) { g_deg[i] = 1.0f; g_cnt[i] = 0; }
    if (i < NG * HID) g_psum[i] = 0.0f;
    if (i < NG) g_pcnt[i] = 0.0f;
}

// ---------------- degree + in-degree counts ----------------
__global__ void k_deg(const int* __restrict__ col, const float* __restrict__ ew, int e) {
    int i = blockIdx.x * blockDim.x + threadIdx.x;
    if (i < e) {
        int c = col[i];
        atomicAdd(&g_deg[c], ew[i]);
        atomicAdd(&g_cnt[c], 1);
    }
}

__global__ void k_dinv(int n) {
    int i = blockIdx.x * blockDim.x + threadIdx.x;
    if (i < n) g_dinv[i] = rsqrtf(g_deg[i]);  // deg >= 1 always (self loop)
}

// ---------------- 3-phase exclusive scan of g_cnt -> g_off ----------------
__device__ __forceinline__ int warp_incl_scan(int x, int lane) {
#pragma unroll
    for (int d = 1; d < 32; d <<= 1) {
        int t = __shfl_up_sync(0xFFFFFFFFu, x, d);
        if (lane >= d) x += t;
    }
    return x;
}

__global__ void k_scan1(int n) {
    __shared__ int wsum[32];
    int tid = threadIdx.x;
    int gid = blockIdx.x * 1024 + tid;
    int v = (gid < n) ? g_cnt[gid] : 0;
    int lane = tid & 31, wid = tid >> 5;
    int x = warp_incl_scan(v, lane);
    if (lane == 31) wsum[wid] = x;
    __syncthreads();
    if (tid < 32) wsum[tid] = warp_incl_scan(wsum[tid], tid);
    __syncthreads();
    int base = (wid > 0) ? wsum[wid - 1] : 0;
    int incl = base + x;
    if (gid < n) g_off[gid] = incl - v;          // block-local exclusive
    if (tid == 1023) g_bsum[blockIdx.x] = incl;  // block total (padding = 0)
}

__global__ void k_scan2(int nb) {
    __shared__ int wsum[32];
    int tid = threadIdx.x;
    int v = (tid < nb) ? g_bsum[tid] : 0;
    int lane = tid & 31, wid = tid >> 5;
    int x = warp_incl_scan(v, lane);
    if (lane == 31) wsum[wid] = x;
    __syncthreads();
    if (tid < 32) wsum[tid] = warp_incl_scan(wsum[tid], tid);
    __syncthreads();
    int base = (wid > 0) ? wsum[wid - 1] : 0;
    if (tid < nb) g_bsum[tid] = base + x - v;    // exclusive
}

__global__ void k_scan3(int n) {
    int gid = blockIdx.x * 1024 + threadIdx.x;
    if (gid < n) {
        int o = g_off[gid] + g_bsum[blockIdx.x];
        g_off[gid] = o;
        g_cur[gid] = o;
    }
}

// ---------------- CSC scatter: (row, dinv[row]*w*dinv[col]) per incoming edge ----------------
__global__ void k_scatter(const int* __restrict__ row, const int* __restrict__ col,
                          const float* __restrict__ ew, int e) {
    int i = blockIdx.x * blockDim.x + threadIdx.x;
    if (i < e) {
        int r = row[i], c = col[i];
        int p = atomicAdd(&g_cur[c], 1);
        g_csc_row[p] = r;
        g_csc_w[p] = g_dinv[r] * ew[i] * g_dinv[c];
    }
}

// ---------------- tiled fp32 GEMM: C[n,64] = A[n,K] @ W[K,64] ----------------
template <int K>
__global__ void k_gemm(const float* __restrict__ A, const float* __restrict__ W,
                       float* __restrict__ C, int n) {
    __shared__ float sA[64][33];   // padded to kill bank conflicts on column reads
    __shared__ float sW[32][64];
    int row0 = blockIdx.x * 64;
    int tid = threadIdx.x;
    int ty = tid >> 4;   // 0..15 -> 4 rows each
    int tx = tid & 15;   // 0..15 -> 4 cols each

    float acc[4][4];
#pragma unroll
    for (int i = 0; i < 4; i++)
#pragma unroll
        for (int j = 0; j < 4; j++) acc[i][j] = 0.0f;

#pragma unroll
    for (int k0 = 0; k0 < K; k0 += 32) {
        // Stage A tile [64][32] and W tile [32][64]
#pragma unroll
        for (int t = 0; t < 2; t++) {
            int id = tid + t * 256;
            int r = id >> 3, q = id & 7;                 // 64 rows x 8 float4
            int row = row0 + r;
            float4 v = make_float4(0.f, 0.f, 0.f, 0.f);
            if (row < n) v = *(const float4*)&A[(size_t)row * K + k0 + q * 4];
            sA[r][q * 4 + 0] = v.x; sA[r][q * 4 + 1] = v.y;
            sA[r][q * 4 + 2] = v.z; sA[r][q * 4 + 3] = v.w;

            int wr = id >> 4, wq = id & 15;              // 32 rows x 16 float4
            *(float4*)&sW[wr][wq * 4] = *(const float4*)&W[(size_t)(k0 + wr) * 64 + wq * 4];
        }
        __syncthreads();
#pragma unroll
        for (int kk = 0; kk < 32; kk++) {
            float ra[4];
#pragma unroll
            for (int i = 0; i < 4; i++) ra[i] = sA[ty * 4 + i][kk];
            float4 rb = *(const float4*)&sW[kk][tx * 4];
#pragma unroll
            for (int i = 0; i < 4; i++) {
                acc[i][0] += ra[i] * rb.x;
                acc[i][1] += ra[i] * rb.y;
                acc[i][2] += ra[i] * rb.z;
                acc[i][3] += ra[i] * rb.w;
            }
        }
        __syncthreads();
    }
#pragma unroll
    for (int i = 0; i < 4; i++) {
        int row = row0 + ty * 4 + i;
        if (row < n)
            *(float4*)&C[(size_t)row * 64 + tx * 4] =
                make_float4(acc[i][0], acc[i][1], acc[i][2], acc[i][3]);
    }
}

// ---------------- gather aggregation: one warp per node, float2 per lane ----------------
__global__ void k_agg(const float* __restrict__ Hin, float* __restrict__ Hout,
                      const float* __restrict__ bias, int n) {
    int warp = (blockIdx.x * blockDim.x + threadIdx.x) >> 5;
    int lane = threadIdx.x & 31;
    if (warp >= n) return;
    int nd = warp;
    const float2* hp = (const float2*)Hin;
    float di = g_dinv[nd];
    float wself = di * di;                     // self-loop norm
    float2 hv = hp[(size_t)nd * 32 + lane];
    float2 acc = make_float2(hv.x * wself, hv.y * wself);
    int s = g_off[nd];
    int e = s + g_cnt[nd];
    for (int i = s; i < e; i++) {
        int r = __ldg(&g_csc_row[i]);
        float wt = __ldg(&g_csc_w[i]);
        float2 v = hp[(size_t)r * 32 + lane];
        acc.x += wt * v.x;
        acc.y += wt * v.y;
    }
    float2 bb = ((const float2*)bias)[lane];
    acc.x = fmaxf(acc.x + bb.x, 0.0f);
    acc.y = fmaxf(acc.y + bb.y, 0.0f);
    ((float2*)Hout)[(size_t)nd * 32 + lane] = acc;
}

// ---------------- pooling: b is sorted; run-length accumulate, rare atomic flushes ----------------
#define POOL_CH 256
__global__ void k_pool(const float* __restrict__ Hin, const int* __restrict__ b, int n) {
    int j = threadIdx.x;  // 0..63 feature
    int base = blockIdx.x * POOL_CH;
    int end = base + POOL_CH;
    if (end > n) end = n;
    float acc = 0.0f;
    int cur = -1, cnt = 0;
    for (int i = base; i < end; i++) {
        int g = __ldg(&b[i]);
        if (g != cur) {
            if (cur >= 0) {
                atomicAdd(&g_psum[cur * 64 + j], acc);
                if (j == 0) atomicAdd(&g_pcnt[cur], (float)cnt);
            }
            cur = g; acc = 0.0f; cnt = 0;
        }
        acc += __ldg(&Hin[(size_t)i * 64 + j]);
        cnt++;
    }
    if (cur >= 0) {
        atomicAdd(&g_psum[cur * 64 + j], acc);
        if (j == 0) atomicAdd(&g_pcnt[cur], (float)cnt);
    }
}

// ---------------- head: mean + Linear(64,32)+ReLU + Linear(32,1) ----------------
__global__ void k_head(float* __restrict__ out,
                       const float* __restrict__ Wm1, const float* __restrict__ bm1,
                       const float* __restrict__ Wm2, const float* __restrict__ bm2) {
    int g = threadIdx.x;  // 0..63
    float inv = 1.0f / fmaxf(g_pcnt[g], 1.0f);
    float p[64];
#pragma unroll
    for (int j = 0; j < 64; j++) p[j] = g_psum[g * 64 + j] * inv;
    float o = 0.0f;
#pragma unroll 4
    for (int m = 0; m < 32; m++) {
        float t = bm1[m];
#pragma unroll
        for (int j = 0; j < 64; j++) t += p[j] * Wm1[j * 32 + m];
        t = fmaxf(t, 0.0f);
        o += t * Wm2[m];
    }
    out[g] = o + bm2[0];
}

// ---------------- launch ----------------
extern "C" void kernel_launch(void* const* d_in, const int* in_sizes, int n_in,
                              void* d_out, int out_size) {
    const float* x   = (const float*)d_in[0];
    const int*   ei  = (const int*)d_in[1];
    const float* ew  = (const float*)d_in[2];
    const int*   b   = (const int*)d_in[3];
    const float* W1  = (const float*)d_in[4];
    const float* b1  = (const float*)d_in[5];
    const float* W2  = (const float*)d_in[6];
    const float* b2  = (const float*)d_in[7];
    const float* Wm1 = (const float*)d_in[8];
    const float* bm1 = (const float*)d_in[9];
    const float* Wm2 = (const float*)d_in[10];
    const float* bm2 = (const float*)d_in[11];
    float* out = (float*)d_out;

    const int E = in_sizes[2];   // ew element count
    const int N = in_sizes[3];   // b element count
    const int* row = ei;
    const int* col = ei + E;

    int nb256_N = (N + 255) / 256;
    int nb256_E = (E + 255) / 256;
    int nb1024  = (N + 1023) / 1024;

    // graph build
    k_init<<<nb256_N, 256>>>(N);
    k_deg<<<nb256_E, 256>>>(col, ew, E);
    k_dinv<<<nb256_N, 256>>>(N);
    k_scan1<<<nb1024, 1024>>>(N);
    k_scan2<<<1, 1024>>>(nb1024);
    k_scan3<<<nb1024, 1024>>>(N);
    k_scatter<<<nb256_E, 256>>>(row, col, ew, E);

    // layer 1
    k_gemm<DIM><<<(N + 63) / 64, 256>>>(x, W1, g_bufA, N);
    k_agg<<<(N * 32 + 255) / 256, 256>>>(g_bufA, g_bufB, b1, N);

    // layer 2
    k_gemm<HID><<<(N + 63) / 64, 256>>>(g_bufB, W2, g_bufA, N);
    k_agg<<<(N * 32 + 255) / 256, 256>>>(g_bufA, g_bufB, b2, N);

    // pool + head
    k_pool<<<(N + POOL_CH - 1) / POOL_CH, 64>>>(g_bufB, b, N);
    k_head<<<1, 64>>>(out, Wm1, bm1, Wm2, bm2);
}